// round 3
// baseline (speedup 1.0000x reference)
#include <cuda_runtime.h>

#define NTOK 4096
#define EMB  768
#define NH   12
#define HD   64

// Scratch (allocation-free: device globals)
__device__ float g_q[NH * NTOK * HD];
__device__ float g_k[NH * NTOK * HD];
__device__ float g_v[NH * NTOK * HD];
__device__ float g_ao[NTOK * EMB];

// ---------------------------------------------------------------------------
// C = A(M x K) @ W^T + bias, M=4096, K=768, Nout=768.
// mode 0/1/2: write to g_q/g_k/g_v in [H][N][64] layout. mode 3: read g_ao,
// write outp in [N][768] layout.
// Tiles: 64x64, BK=16, 256 threads, 4x4 micro-tile per thread.
// ---------------------------------------------------------------------------
__global__ __launch_bounds__(256) void gemm_kernel(
    const float* __restrict__ A_in, const float* __restrict__ W,
    const float* __restrict__ bias, float* __restrict__ outp, int mode)
{
    __shared__ float As[64][17];
    __shared__ float Bs[64][17];

    const float* A = (mode == 3) ? g_ao : A_in;

    int jb  = blockIdx.x * 64;
    int mb  = blockIdx.y * 64;
    int tid = threadIdx.x;
    int tx  = tid & 15, ty = tid >> 4;
    int r0  = ty * 4,  c0 = tx * 4;
    int lr  = tid >> 2;
    int lc  = (tid & 3) << 2;

    float acc[4][4] = {};

    for (int k0 = 0; k0 < EMB; k0 += 16) {
        float4 av = *(const float4*)(A + (size_t)(mb + lr) * EMB + k0 + lc);
        As[lr][lc + 0] = av.x; As[lr][lc + 1] = av.y;
        As[lr][lc + 2] = av.z; As[lr][lc + 3] = av.w;
        float4 bv = *(const float4*)(W + (size_t)(jb + lr) * EMB + k0 + lc);
        Bs[lr][lc + 0] = bv.x; Bs[lr][lc + 1] = bv.y;
        Bs[lr][lc + 2] = bv.z; Bs[lr][lc + 3] = bv.w;
        __syncthreads();

        #pragma unroll
        for (int kk = 0; kk < 16; kk++) {
            float a[4], b[4];
            #pragma unroll
            for (int i = 0; i < 4; i++) a[i] = As[r0 + i][kk];
            #pragma unroll
            for (int j = 0; j < 4; j++) b[j] = Bs[c0 + j][kk];
            #pragma unroll
            for (int i = 0; i < 4; i++)
                #pragma unroll
                for (int j = 0; j < 4; j++)
                    acc[i][j] = fmaf(a[i], b[j], acc[i][j]);
        }
        __syncthreads();
    }

    #pragma unroll
    for (int i = 0; i < 4; i++) {
        int gr = mb + r0 + i;
        #pragma unroll
        for (int j = 0; j < 4; j++) {
            int jc = jb + c0 + j;
            float val = acc[i][j] + bias[jc];
            if (mode == 3) {
                outp[(size_t)gr * EMB + jc] = val;
            } else {
                int h = jc >> 6, d = jc & 63;
                float* dst = (mode == 0) ? g_q : (mode == 1) ? g_k : g_v;
                dst[((size_t)h * NTOK + gr) * HD + d] = val;
            }
        }
    }
}

// ---------------------------------------------------------------------------
// Flash-style attention. Block = (64 query rows) x (1 head). 256 threads,
// each owns a 4x4 micro-tile of the 64x64 score tile / output tile.
// Online softmax: m, l per row kept redundantly in the 4 threads of a row
// (consistent via shfl reductions over the 16-lane row group).
// Bias: +1.0 per occurrence of column index in similarity_matrix[row].
// ---------------------------------------------------------------------------
__global__ __launch_bounds__(256) void attn_kernel(const int* __restrict__ sim)
{
    extern __shared__ float smf[];
    float* Qs = smf;                 // 64*65
    float* Ks = Qs + 64 * 65;        // 64*65
    float* Vs = Ks + 64 * 65;        // 64*65
    float* Ps = Vs + 64 * 65;        // 64*65
    int*  sims = (int*)(Ps + 64 * 65); // 64*10

    int h   = blockIdx.y;
    int i0  = blockIdx.x * 64;
    int tid = threadIdx.x;
    int tx  = tid & 15, ty = tid >> 4;
    int r0  = ty * 4,  c0 = tx * 4;

    const float* qb = g_q + ((size_t)h * NTOK + i0) * HD;
    const float* kb = g_k + (size_t)h * NTOK * HD;
    const float* vb = g_v + (size_t)h * NTOK * HD;

    // Load Q tile (64x64) into smem
    for (int t = tid; t < 64 * 16; t += 256) {
        int r = t >> 4, c4 = (t & 15) << 2;
        float4 v4 = *(const float4*)(qb + (size_t)r * HD + c4);
        Qs[r * 65 + c4 + 0] = v4.x; Qs[r * 65 + c4 + 1] = v4.y;
        Qs[r * 65 + c4 + 2] = v4.z; Qs[r * 65 + c4 + 3] = v4.w;
    }
    // Load similarity indices for these 64 rows (10 ints per row)
    for (int t = tid; t < 64 * 10; t += 256)
        sims[t] = sim[(size_t)(i0 + t / 10) * 10 + (t % 10)];

    float m[4], l[4], o[4][4];
    #pragma unroll
    for (int i = 0; i < 4; i++) {
        m[i] = -1e30f; l[i] = 0.f;
        #pragma unroll
        for (int j = 0; j < 4; j++) o[i][j] = 0.f;
    }

    for (int kt = 0; kt < NTOK / 64; kt++) {
        int j0 = kt * 64;
        __syncthreads();  // protect Ks/Vs/Ps from previous iteration's readers
        for (int t = tid; t < 64 * 16; t += 256) {
            int r = t >> 4, c4 = (t & 15) << 2;
            float4 kv = *(const float4*)(kb + (size_t)(j0 + r) * HD + c4);
            Ks[r * 65 + c4 + 0] = kv.x; Ks[r * 65 + c4 + 1] = kv.y;
            Ks[r * 65 + c4 + 2] = kv.z; Ks[r * 65 + c4 + 3] = kv.w;
            float4 vv = *(const float4*)(vb + (size_t)(j0 + r) * HD + c4);
            Vs[r * 65 + c4 + 0] = vv.x; Vs[r * 65 + c4 + 1] = vv.y;
            Vs[r * 65 + c4 + 2] = vv.z; Vs[r * 65 + c4 + 3] = vv.w;
        }
        __syncthreads();

        // S = Q K^T
        float s[4][4] = {};
        #pragma unroll 8
        for (int d = 0; d < HD; d++) {
            float a[4], b[4];
            #pragma unroll
            for (int i = 0; i < 4; i++) a[i] = Qs[(r0 + i) * 65 + d];
            #pragma unroll
            for (int j = 0; j < 4; j++) b[j] = Ks[(c0 + j) * 65 + d];
            #pragma unroll
            for (int i = 0; i < 4; i++)
                #pragma unroll
                for (int j = 0; j < 4; j++)
                    s[i][j] = fmaf(a[i], b[j], s[i][j]);
        }
        #pragma unroll
        for (int i = 0; i < 4; i++)
            #pragma unroll
            for (int j = 0; j < 4; j++) s[i][j] *= 0.125f;

        // Sparse bias: +1.0 per occurrence (duplicates accumulate)
        #pragma unroll
        for (int i = 0; i < 4; i++) {
            #pragma unroll
            for (int k2 = 0; k2 < 10; k2++) {
                int rel = sims[(r0 + i) * 10 + k2] - j0;
                if ((unsigned)rel < 64u) {
                    int rc = rel - c0;
                    s[i][0] += (rc == 0) ? 1.f : 0.f;
                    s[i][1] += (rc == 1) ? 1.f : 0.f;
                    s[i][2] += (rc == 2) ? 1.f : 0.f;
                    s[i][3] += (rc == 3) ? 1.f : 0.f;
                }
            }
        }

        // Online softmax update (row group = 16 consecutive lanes)
        #pragma unroll
        for (int i = 0; i < 4; i++) {
            float mx = fmaxf(fmaxf(s[i][0], s[i][1]), fmaxf(s[i][2], s[i][3]));
            #pragma unroll
            for (int off = 8; off >= 1; off >>= 1)
                mx = fmaxf(mx, __shfl_xor_sync(0xffffffffu, mx, off));
            float mn    = fmaxf(m[i], mx);
            float alpha = __expf(m[i] - mn);
            float rs = 0.f;
            #pragma unroll
            for (int j = 0; j < 4; j++) {
                float p = __expf(s[i][j] - mn);
                Ps[(r0 + i) * 65 + c0 + j] = p;
                rs += p;
            }
            #pragma unroll
            for (int off = 8; off >= 1; off >>= 1)
                rs += __shfl_xor_sync(0xffffffffu, rs, off);
            l[i] = l[i] * alpha + rs;
            #pragma unroll
            for (int j = 0; j < 4; j++) o[i][j] *= alpha;
            m[i] = mn;
        }
        __syncthreads();  // Ps fully written before PV

        // O += P @ V
        #pragma unroll 8
        for (int c = 0; c < 64; c++) {
            float p[4], vv[4];
            #pragma unroll
            for (int i = 0; i < 4; i++) p[i] = Ps[(r0 + i) * 65 + c];
            #pragma unroll
            for (int j = 0; j < 4; j++) vv[j] = Vs[c * 65 + c0 + j];
            #pragma unroll
            for (int i = 0; i < 4; i++)
                #pragma unroll
                for (int j = 0; j < 4; j++)
                    o[i][j] = fmaf(p[i], vv[j], o[i][j]);
        }
    }

    #pragma unroll
    for (int i = 0; i < 4; i++) {
        float inv = 1.f / l[i];
        #pragma unroll
        for (int j = 0; j < 4; j++)
            g_ao[(size_t)(i0 + r0 + i) * EMB + h * HD + c0 + j] = o[i][j] * inv;
    }
}

// ---------------------------------------------------------------------------
extern "C" void kernel_launch(void* const* d_in, const int* in_sizes, int n_in,
                              void* d_out, int out_size)
{
    const float* x  = (const float*)d_in[0];
    const int*   sim = (const int*)d_in[1];
    const float* Wq = (const float*)d_in[2];
    const float* bq = (const float*)d_in[3];
    const float* Wk = (const float*)d_in[4];
    const float* bk = (const float*)d_in[5];
    const float* Wv = (const float*)d_in[6];
    const float* bv = (const float*)d_in[7];
    const float* Wo = (const float*)d_in[8];
    const float* bo = (const float*)d_in[9];
    float* out = (float*)d_out;

    const int smem = (4 * 64 * 65) * (int)sizeof(float) + 640 * (int)sizeof(int);
    cudaFuncSetAttribute(attn_kernel,
                         cudaFuncAttributeMaxDynamicSharedMemorySize, smem);

    dim3 gg(EMB / 64, NTOK / 64);
    gemm_kernel<<<gg, 256>>>(x, Wq, bq, nullptr, 0);
    gemm_kernel<<<gg, 256>>>(x, Wk, bk, nullptr, 1);
    gemm_kernel<<<gg, 256>>>(x, Wv, bv, nullptr, 2);
    attn_kernel<<<dim3(NTOK / 64, NH), 256, smem>>>(sim);
    gemm_kernel<<<gg, 256>>>(nullptr, Wo, bo, out, 3);
}

// round 6
// speedup vs baseline: 2.5833x; 2.5833x over previous
#include <cuda_runtime.h>
#include <cuda_bf16.h>
#include <cstdint>

#define NTOK 4096
#define EMB  768
#define NH   12
#define HD   64
#define PADB 72
#define L2E  1.4426950408889634f

// ---------------------------------------------------------------------------
// Scratch (allocation-free device globals)
// ---------------------------------------------------------------------------
__device__ __align__(16) __nv_bfloat16 g_xhi[NTOK * EMB];
__device__ __align__(16) __nv_bfloat16 g_xlo[NTOK * EMB];
__device__ __align__(16) __nv_bfloat16 g_whi[EMB * EMB];
__device__ __align__(16) __nv_bfloat16 g_wlo[EMB * EMB];
__device__ __align__(16) __nv_bfloat16 g_qhi[NH * NTOK * HD];
__device__ __align__(16) __nv_bfloat16 g_qlo[NH * NTOK * HD];
__device__ __align__(16) __nv_bfloat16 g_khi[NH * NTOK * HD];
__device__ __align__(16) __nv_bfloat16 g_klo[NH * NTOK * HD];
__device__ __align__(16) __nv_bfloat16 g_vhi[NH * NTOK * HD];
__device__ __align__(16) __nv_bfloat16 g_vlo[NH * NTOK * HD];
__device__ __align__(16) __nv_bfloat16 g_vthi[NH * HD * NTOK];
__device__ __align__(16) __nv_bfloat16 g_vtlo[NH * HD * NTOK];
__device__ float g_ao[NTOK * EMB];

// ---------------------------------------------------------------------------
// Helpers
// ---------------------------------------------------------------------------
__device__ __forceinline__ uint32_t pack_bf16x2(float lo, float hi) {
    uint32_t r;
    asm("cvt.rn.bf16x2.f32 %0, %1, %2;" : "=r"(r) : "f"(hi), "f"(lo));
    return r;
}

// fast exp2 on the FMA pipe (no MUFU), |rel err| ~ 2.4e-6, input <= 0
__device__ __forceinline__ float exp2p(float t) {
    t = fmaxf(t, -120.f);
    float fi = rintf(t);
    float f = t - fi;
    float p = 0.00133335581f;
    p = fmaf(p, f, 0.00961812911f);
    p = fmaf(p, f, 0.0555041087f);
    p = fmaf(p, f, 0.240226507f);
    p = fmaf(p, f, 0.69314718056f);
    p = fmaf(p, f, 1.0f);
    return p * __int_as_float(((int)fi + 127) << 23);
}

#define MMA_BF16(d, a, b0, b1)                                             \
    asm volatile(                                                          \
        "mma.sync.aligned.m16n8k16.row.col.f32.bf16.bf16.f32 "            \
        "{%0,%1,%2,%3}, {%4,%5,%6,%7}, {%8,%9}, {%0,%1,%2,%3};"           \
        : "+f"((d)[0]), "+f"((d)[1]), "+f"((d)[2]), "+f"((d)[3])           \
        : "r"((a)[0]), "r"((a)[1]), "r"((a)[2]), "r"((a)[3]),              \
          "r"(b0), "r"(b1))

// ---------------------------------------------------------------------------
// fp32 -> (bf16 hi, bf16 lo) split. dst_w: 0 -> g_xhi/g_xlo, 1 -> g_whi/g_wlo.
// from_gao: read g_ao instead of src_in.
// ---------------------------------------------------------------------------
__global__ __launch_bounds__(256) void convert_split(const float* __restrict__ src_in,
                                                     int n4, int dst_w, int from_gao)
{
    int i = blockIdx.x * blockDim.x + threadIdx.x;
    if (i >= n4) return;
    const float* src = from_gao ? g_ao : src_in;
    __nv_bfloat16* hi = dst_w ? g_whi : g_xhi;
    __nv_bfloat16* lo = dst_w ? g_wlo : g_xlo;

    float4 v = ((const float4*)src)[i];
    uint32_t h0 = pack_bf16x2(v.x, v.y);
    uint32_t h1 = pack_bf16x2(v.z, v.w);
    float r0 = v.x - __uint_as_float(h0 << 16);
    float r1 = v.y - __uint_as_float(h0 & 0xffff0000u);
    float r2 = v.z - __uint_as_float(h1 << 16);
    float r3 = v.w - __uint_as_float(h1 & 0xffff0000u);
    ((uint32_t*)hi)[2 * i + 0] = h0;
    ((uint32_t*)hi)[2 * i + 1] = h1;
    ((uint32_t*)lo)[2 * i + 0] = pack_bf16x2(r0, r1);
    ((uint32_t*)lo)[2 * i + 1] = pack_bf16x2(r2, r3);
}

// ---------------------------------------------------------------------------
// mma.sync bf16-split GEMM: C = A(4096x768) @ W^T + bias.
// A = g_xhi/g_xlo, W = g_whi/g_wlo. Block: 64(M) x 64(N), 4 warps x 16 rows.
// mode 0/1/2: emit bf16 hi/lo into g_{q,k,v}{hi,lo} [h][tok][64].
// mode 3: emit fp32 into outp [N][768].
// ---------------------------------------------------------------------------
__global__ __launch_bounds__(128, 1) void gemm_tc(const float* __restrict__ bias,
                                                  float* __restrict__ outp, int mode)
{
    __shared__ __nv_bfloat16 Ah[64][PADB], Al[64][PADB];
    __shared__ __nv_bfloat16 Bh[64][PADB], Bl[64][PADB];

    int nb = blockIdx.x * 64, mb = blockIdx.y * 64;
    int tid = threadIdx.x, w = tid >> 5, lane = tid & 31;
    int qr = lane >> 2, qc = (lane & 3) * 2;

    float acc[8][4];
    #pragma unroll
    for (int n = 0; n < 8; n++)
        #pragma unroll
        for (int j = 0; j < 4; j++) acc[n][j] = 0.f;

    for (int kc = 0; kc < EMB / 64; kc++) {
        __syncthreads();
        for (int idx = tid; idx < 512; idx += 128) {
            int r = idx >> 3, c = idx & 7;
            const char* sa = (const char*)(g_xhi + (size_t)(mb + r) * EMB + kc * 64) + c * 16;
            const char* sal = (const char*)(g_xlo + (size_t)(mb + r) * EMB + kc * 64) + c * 16;
            const char* sb = (const char*)(g_whi + (size_t)(nb + r) * EMB + kc * 64) + c * 16;
            const char* sbl = (const char*)(g_wlo + (size_t)(nb + r) * EMB + kc * 64) + c * 16;
            *(uint4*)((char*)&Ah[r][0] + c * 16) = *(const uint4*)sa;
            *(uint4*)((char*)&Al[r][0] + c * 16) = *(const uint4*)sal;
            *(uint4*)((char*)&Bh[r][0] + c * 16) = *(const uint4*)sb;
            *(uint4*)((char*)&Bl[r][0] + c * 16) = *(const uint4*)sbl;
        }
        __syncthreads();

        #pragma unroll
        for (int t = 0; t < 4; t++) {
            uint32_t ah[4], al[4];
            #pragma unroll
            for (int j = 0; j < 4; j++) {
                int r = w * 16 + qr + (j & 1) * 8;
                int c = t * 16 + qc + (j >> 1) * 8;
                ah[j] = *(const uint32_t*)&Ah[r][c];
                al[j] = *(const uint32_t*)&Al[r][c];
            }
            #pragma unroll
            for (int n = 0; n < 8; n++) {
                int br = n * 8 + qr, bcl = t * 16 + qc;
                uint32_t bh0 = *(const uint32_t*)&Bh[br][bcl];
                uint32_t bh1 = *(const uint32_t*)&Bh[br][bcl + 8];
                uint32_t bl0 = *(const uint32_t*)&Bl[br][bcl];
                uint32_t bl1 = *(const uint32_t*)&Bl[br][bcl + 8];
                MMA_BF16(acc[n], ah, bh0, bh1);
                MMA_BF16(acc[n], ah, bl0, bl1);
                MMA_BF16(acc[n], al, bh0, bh1);
            }
        }
    }

    int r0 = mb + w * 16 + qr;
    if (mode == 3) {
        #pragma unroll
        for (int n = 0; n < 8; n++) {
            int col = nb + n * 8 + qc;
            float2 v0 = {acc[n][0] + bias[col], acc[n][1] + bias[col + 1]};
            float2 v1 = {acc[n][2] + bias[col], acc[n][3] + bias[col + 1]};
            *(float2*)(outp + (size_t)r0 * EMB + col) = v0;
            *(float2*)(outp + (size_t)(r0 + 8) * EMB + col) = v1;
        }
    } else {
        __nv_bfloat16* dh = (mode == 0) ? g_qhi : (mode == 1) ? g_khi : g_vhi;
        __nv_bfloat16* dl = (mode == 0) ? g_qlo : (mode == 1) ? g_klo : g_vlo;
        int hh = nb >> 6;
        #pragma unroll
        for (int n = 0; n < 8; n++) {
            int d = n * 8 + qc;
            float b0 = bias[nb + d], b1 = bias[nb + d + 1];
            #pragma unroll
            for (int half = 0; half < 2; half++) {
                float v0 = acc[n][half * 2 + 0] + b0;
                float v1 = acc[n][half * 2 + 1] + b1;
                uint32_t ph = pack_bf16x2(v0, v1);
                float e0 = v0 - __uint_as_float(ph << 16);
                float e1 = v1 - __uint_as_float(ph & 0xffff0000u);
                size_t off = ((size_t)hh * NTOK + r0 + half * 8) * HD + d;
                *(uint32_t*)(dh + off) = ph;
                *(uint32_t*)(dl + off) = pack_bf16x2(e0, e1);
            }
        }
    }
}

// ---------------------------------------------------------------------------
// V transpose: g_v{hi,lo} [h][tok][64] -> g_vt{hi,lo} [h][64][tok]
// ---------------------------------------------------------------------------
__global__ __launch_bounds__(256) void transpose_v()
{
    __shared__ __nv_bfloat16 th[64][PADB], tl[64][PADB];
    int h = blockIdx.y, j0 = blockIdx.x * 64, tid = threadIdx.x;

    for (int idx = tid; idx < 512; idx += 256) {
        int r = idx >> 3, c = idx & 7;
        const char* sh = (const char*)(g_vhi + ((size_t)h * NTOK + j0 + r) * HD) + c * 16;
        const char* sl = (const char*)(g_vlo + ((size_t)h * NTOK + j0 + r) * HD) + c * 16;
        *(uint4*)((char*)&th[r][0] + c * 16) = *(const uint4*)sh;
        *(uint4*)((char*)&tl[r][0] + c * 16) = *(const uint4*)sl;
    }
    __syncthreads();

    for (int odx = tid; odx < 2048; odx += 256) {
        int d = odx >> 5, tk = (odx & 31) * 2;
        uint32_t ph = ((uint32_t)__bfloat16_as_ushort(th[tk][d])) |
                      ((uint32_t)__bfloat16_as_ushort(th[tk + 1][d]) << 16);
        uint32_t pl = ((uint32_t)__bfloat16_as_ushort(tl[tk][d])) |
                      ((uint32_t)__bfloat16_as_ushort(tl[tk + 1][d]) << 16);
        size_t off = ((size_t)h * HD + d) * NTOK + j0 + tk;
        *(uint32_t*)(g_vthi + off) = ph;
        *(uint32_t*)(g_vtlo + off) = pl;
    }
}

// ---------------------------------------------------------------------------
// Tensor-core flash attention. Block = 64 queries x 1 head, 4 warps x 16 rows.
// QK^T and PV on mma.sync bf16-split; softmax via poly-exp2 (FMA pipe).
// Sparse bias via per-tile u8 count scatter (exact: +1.0 * count, pre-max).
// ---------------------------------------------------------------------------
__global__ __launch_bounds__(128, 1) void attn_tc(const int* __restrict__ sim)
{
    __shared__ __nv_bfloat16 Kh[64][PADB], Kl[64][PADB];
    __shared__ __nv_bfloat16 Vh[64][PADB], Vl[64][PADB];   // [d][tok]
    __shared__ __align__(16) unsigned char bc[64][64];
    __shared__ int sims[640];

    int h = blockIdx.y, i0 = blockIdx.x * 64;
    int tid = threadIdx.x, w = tid >> 5, lane = tid & 31;
    int qr = lane >> 2, qc = (lane & 3) * 2;

    for (int t = tid; t < 640; t += 128) sims[t] = sim[(size_t)i0 * 10 + t];

    // Persistent Q fragments from global (bf16 pairs are b32-aligned)
    uint32_t qh[4][4], ql[4][4];
    {
        const __nv_bfloat16* qbh = g_qhi + ((size_t)h * NTOK + i0 + w * 16) * HD;
        const __nv_bfloat16* qbl = g_qlo + ((size_t)h * NTOK + i0 + w * 16) * HD;
        #pragma unroll
        for (int t = 0; t < 4; t++)
            #pragma unroll
            for (int j = 0; j < 4; j++) {
                int r = qr + (j & 1) * 8;
                int c = t * 16 + qc + (j >> 1) * 8;
                qh[t][j] = *(const uint32_t*)(qbh + (size_t)r * HD + c);
                ql[t][j] = *(const uint32_t*)(qbl + (size_t)r * HD + c);
            }
    }

    const __nv_bfloat16* kbh = g_khi + (size_t)h * NTOK * HD;
    const __nv_bfloat16* kbl = g_klo + (size_t)h * NTOK * HD;
    const __nv_bfloat16* vbh = g_vthi + (size_t)h * HD * NTOK;
    const __nv_bfloat16* vbl = g_vtlo + (size_t)h * HD * NTOK;

    float o[8][4];
    #pragma unroll
    for (int n = 0; n < 8; n++)
        #pragma unroll
        for (int j = 0; j < 4; j++) o[n][j] = 0.f;
    float m0 = -1e30f, m1 = -1e30f, l0 = 0.f, l1 = 0.f;
    int br0 = w * 16 + qr, br1 = br0 + 8;

    for (int kt = 0; kt < NTOK / 64; kt++) {
        int j0 = kt * 64;
        __syncthreads();
        for (int idx = tid; idx < 512; idx += 128) {
            int r = idx >> 3, c = idx & 7;
            *(uint4*)((char*)&Kh[r][0] + c * 16) =
                *(const uint4*)((const char*)(kbh + (size_t)(j0 + r) * HD) + c * 16);
            *(uint4*)((char*)&Kl[r][0] + c * 16) =
                *(const uint4*)((const char*)(kbl + (size_t)(j0 + r) * HD) + c * 16);
            *(uint4*)((char*)&Vh[r][0] + c * 16) =
                *(const uint4*)((const char*)(vbh + (size_t)r * NTOK + j0) + c * 16);
            *(uint4*)((char*)&Vl[r][0] + c * 16) =
                *(const uint4*)((const char*)(vbl + (size_t)r * NTOK + j0) + c * 16);
        }
        for (int idx = tid; idx < 256; idx += 128)
            *(uint4*)(&bc[0][0] + idx * 16) = make_uint4(0u, 0u, 0u, 0u);
        __syncthreads();
        if (tid < 64) {
            #pragma unroll
            for (int s5 = 0; s5 < 10; s5++) {
                int rel = sims[tid * 10 + s5] - j0;
                if ((unsigned)rel < 64u) bc[tid][rel]++;
            }
        }
        __syncthreads();

        // ---- S = Q K^T (3-pass bf16 split) ----
        float s[8][4];
        #pragma unroll
        for (int n = 0; n < 8; n++)
            #pragma unroll
            for (int j = 0; j < 4; j++) s[n][j] = 0.f;
        #pragma unroll
        for (int t = 0; t < 4; t++) {
            #pragma unroll
            for (int n = 0; n < 8; n++) {
                int br = n * 8 + qr, bcl = t * 16 + qc;
                uint32_t bh0 = *(const uint32_t*)&Kh[br][bcl];
                uint32_t bh1 = *(const uint32_t*)&Kh[br][bcl + 8];
                uint32_t bl0 = *(const uint32_t*)&Kl[br][bcl];
                uint32_t bl1 = *(const uint32_t*)&Kl[br][bcl + 8];
                MMA_BF16(s[n], qh[t], bh0, bh1);
                MMA_BF16(s[n], qh[t], bl0, bl1);
                MMA_BF16(s[n], ql[t], bh0, bh1);
            }
        }

        // ---- scale + bias + online softmax ----
        float mx0 = -1e30f, mx1 = -1e30f;
        #pragma unroll
        for (int n = 0; n < 8; n++) {
            int c0i = n * 8 + qc;
            s[n][0] = fmaf(s[n][0], 0.125f, (float)bc[br0][c0i]);
            s[n][1] = fmaf(s[n][1], 0.125f, (float)bc[br0][c0i + 1]);
            s[n][2] = fmaf(s[n][2], 0.125f, (float)bc[br1][c0i]);
            s[n][3] = fmaf(s[n][3], 0.125f, (float)bc[br1][c0i + 1]);
            mx0 = fmaxf(mx0, fmaxf(s[n][0], s[n][1]));
            mx1 = fmaxf(mx1, fmaxf(s[n][2], s[n][3]));
        }
        #pragma unroll
        for (int off = 1; off <= 2; off <<= 1) {
            mx0 = fmaxf(mx0, __shfl_xor_sync(0xffffffffu, mx0, off));
            mx1 = fmaxf(mx1, __shfl_xor_sync(0xffffffffu, mx1, off));
        }
        float mn0 = fmaxf(m0, mx0), mn1 = fmaxf(m1, mx1);
        float a0 = exp2p((m0 - mn0) * L2E), a1 = exp2p((m1 - mn1) * L2E);

        float rs0 = 0.f, rs1 = 0.f;
        uint32_t pa[4][4], pl[4][4];
        #pragma unroll
        for (int n = 0; n < 8; n++) {
            float p0 = exp2p((s[n][0] - mn0) * L2E);
            float p1 = exp2p((s[n][1] - mn0) * L2E);
            float p2 = exp2p((s[n][2] - mn1) * L2E);
            float p3 = exp2p((s[n][3] - mn1) * L2E);
            rs0 += p0 + p1;
            rs1 += p2 + p3;
            uint32_t hp01 = pack_bf16x2(p0, p1);
            uint32_t hp23 = pack_bf16x2(p2, p3);
            float e0 = p0 - __uint_as_float(hp01 << 16);
            float e1 = p1 - __uint_as_float(hp01 & 0xffff0000u);
            float e2 = p2 - __uint_as_float(hp23 << 16);
            float e3 = p3 - __uint_as_float(hp23 & 0xffff0000u);
            int t = n >> 1, half = (n & 1) * 2;
            pa[t][half + 0] = hp01;
            pa[t][half + 1] = hp23;
            pl[t][half + 0] = pack_bf16x2(e0, e1);
            pl[t][half + 1] = pack_bf16x2(e2, e3);
        }
        #pragma unroll
        for (int off = 1; off <= 2; off <<= 1) {
            rs0 += __shfl_xor_sync(0xffffffffu, rs0, off);
            rs1 += __shfl_xor_sync(0xffffffffu, rs1, off);
        }
        l0 = l0 * a0 + rs0;
        l1 = l1 * a1 + rs1;
        m0 = mn0;
        m1 = mn1;
        #pragma unroll
        for (int n = 0; n < 8; n++) {
            o[n][0] *= a0; o[n][1] *= a0;
            o[n][2] *= a1; o[n][3] *= a1;
        }

        // ---- O += P V (3-pass bf16 split) ----
        #pragma unroll
        for (int t = 0; t < 4; t++) {
            #pragma unroll
            for (int n = 0; n < 8; n++) {
                int br = n * 8 + qr, bcl = t * 16 + qc;
                uint32_t bh0 = *(const uint32_t*)&Vh[br][bcl];
                uint32_t bh1 = *(const uint32_t*)&Vh[br][bcl + 8];
                uint32_t bl0 = *(const uint32_t*)&Vl[br][bcl];
                uint32_t bl1 = *(const uint32_t*)&Vl[br][bcl + 8];
                MMA_BF16(o[n], pa[t], bh0, bh1);
                MMA_BF16(o[n], pa[t], bl0, bl1);
                MMA_BF16(o[n], pl[t], bh0, bh1);
            }
        }
    }

    float il0 = 1.f / l0, il1 = 1.f / l1;
    #pragma unroll
    for (int n = 0; n < 8; n++) {
        int col = h * HD + n * 8 + qc;
        float2 v0 = {o[n][0] * il0, o[n][1] * il0};
        float2 v1 = {o[n][2] * il1, o[n][3] * il1};
        *(float2*)(g_ao + (size_t)(i0 + br0) * EMB + col) = v0;
        *(float2*)(g_ao + (size_t)(i0 + br1) * EMB + col) = v1;
    }
}

// ---------------------------------------------------------------------------
extern "C" void kernel_launch(void* const* d_in, const int* in_sizes, int n_in,
                              void* d_out, int out_size)
{
    const float* x   = (const float*)d_in[0];
    const int*   sim = (const int*)d_in[1];
    const float* Wq  = (const float*)d_in[2];
    const float* bq  = (const float*)d_in[3];
    const float* Wk  = (const float*)d_in[4];
    const float* bk  = (const float*)d_in[5];
    const float* Wv  = (const float*)d_in[6];
    const float* bv  = (const float*)d_in[7];
    const float* Wo  = (const float*)d_in[8];
    const float* bo  = (const float*)d_in[9];
    float* out = (float*)d_out;

    const int n4x = NTOK * EMB / 4;
    const int n4w = EMB * EMB / 4;
    dim3 gg(EMB / 64, NTOK / 64);  // (12, 64)

    convert_split<<<n4x / 256, 256>>>(x, n4x, 0, 0);

    convert_split<<<n4w / 256, 256>>>(Wq, n4w, 1, 0);
    gemm_tc<<<gg, 128>>>(bq, nullptr, 0);
    convert_split<<<n4w / 256, 256>>>(Wk, n4w, 1, 0);
    gemm_tc<<<gg, 128>>>(bk, nullptr, 1);
    convert_split<<<n4w / 256, 256>>>(Wv, n4w, 1, 0);
    gemm_tc<<<gg, 128>>>(bv, nullptr, 2);

    transpose_v<<<dim3(NTOK / 64, NH), 256>>>();
    attn_tc<<<dim3(NTOK / 64, NH), 128>>>(sim);

    convert_split<<<n4x / 256, 256>>>(nullptr, n4x, 0, 1);
    convert_split<<<n4w / 256, 256>>>(Wo, n4w, 1, 0);
    gemm_tc<<<gg, 128>>>(bo, out, 3);
}

// round 7
// speedup vs baseline: 3.1923x; 1.2357x over previous
#include <cuda_runtime.h>
#include <cuda_bf16.h>
#include <cstdint>

#define NTOK 4096
#define EMB  768
#define NH   12
#define HD   64
#define PADB 72
#define L2E  1.4426950408889634f

// ---------------------------------------------------------------------------
// Scratch (allocation-free device globals)
// ---------------------------------------------------------------------------
__device__ __align__(16) __nv_bfloat16 g_xhi[NTOK * EMB];
__device__ __align__(16) __nv_bfloat16 g_xlo[NTOK * EMB];
__device__ __align__(16) __nv_bfloat16 g_whi[4 * EMB * EMB];
__device__ __align__(16) __nv_bfloat16 g_wlo[4 * EMB * EMB];
__device__ __align__(16) __nv_bfloat16 g_qhi[NH * NTOK * HD];
__device__ __align__(16) __nv_bfloat16 g_qlo[NH * NTOK * HD];
__device__ __align__(16) __nv_bfloat16 g_khi[NH * NTOK * HD];
__device__ __align__(16) __nv_bfloat16 g_klo[NH * NTOK * HD];
__device__ __align__(16) __nv_bfloat16 g_vhi[NH * NTOK * HD];
__device__ __align__(16) __nv_bfloat16 g_vlo[NH * NTOK * HD];
__device__ __align__(16) __nv_bfloat16 g_vthi[NH * HD * NTOK];
__device__ __align__(16) __nv_bfloat16 g_vtlo[NH * HD * NTOK];
__device__ float g_ao[NTOK * EMB];

// ---------------------------------------------------------------------------
// Helpers
// ---------------------------------------------------------------------------
__device__ __forceinline__ uint32_t pack_bf16x2(float lo, float hi) {
    uint32_t r;
    asm("cvt.rn.bf16x2.f32 %0, %1, %2;" : "=r"(r) : "f"(hi), "f"(lo));
    return r;
}

// fast exp2: FMA pipe only, magic-number round, input <= 0
__device__ __forceinline__ float exp2p(float t) {
    t = fmaxf(t, -120.f);
    float z  = t + 12582912.f;            // 1.5 * 2^23
    float fi = z - 12582912.f;
    float f  = t - fi;
    float p = fmaf(0.00133335581f, f, 0.00961812911f);
    p = fmaf(p, f, 0.0555041087f);
    p = fmaf(p, f, 0.240226507f);
    p = fmaf(p, f, 0.69314718056f);
    p = fmaf(p, f, 1.0f);
    return p * __int_as_float((__float_as_int(z) + 127) << 23);
}

#define MMA_BF16(d, a, b0, b1)                                             \
    asm volatile(                                                          \
        "mma.sync.aligned.m16n8k16.row.col.f32.bf16.bf16.f32 "            \
        "{%0,%1,%2,%3}, {%4,%5,%6,%7}, {%8,%9}, {%0,%1,%2,%3};"           \
        : "+f"((d)[0]), "+f"((d)[1]), "+f"((d)[2]), "+f"((d)[3])           \
        : "r"((a)[0]), "r"((a)[1]), "r"((a)[2]), "r"((a)[3]),              \
          "r"(b0), "r"(b1))

#define LDM_X4(r, a)                                                       \
    asm volatile("ldmatrix.sync.aligned.m8n8.x4.shared.b16 "               \
                 "{%0,%1,%2,%3}, [%4];"                                    \
                 : "=r"((r)[0]), "=r"((r)[1]), "=r"((r)[2]), "=r"((r)[3])  \
                 : "r"(a))

#define CP16(d, s)                                                         \
    asm volatile("cp.async.cg.shared.global [%0], [%1], 16;"               \
                 :: "r"(d), "l"(s))
#define CP_COMMIT() asm volatile("cp.async.commit_group;" ::: "memory")
#define CP_WAIT0()  asm volatile("cp.async.wait_group 0;" ::: "memory")

__device__ __forceinline__ uint32_t sptr(const void* p) {
    return (uint32_t)__cvta_generic_to_shared(p);
}

// ---------------------------------------------------------------------------
// fp32 -> (bf16 hi, bf16 lo) splits
// ---------------------------------------------------------------------------
__device__ __forceinline__ void split_store(__nv_bfloat16* hi, __nv_bfloat16* lo,
                                            int i, float4 v)
{
    uint32_t h0 = pack_bf16x2(v.x, v.y);
    uint32_t h1 = pack_bf16x2(v.z, v.w);
    float r0 = v.x - __uint_as_float(h0 << 16);
    float r1 = v.y - __uint_as_float(h0 & 0xffff0000u);
    float r2 = v.z - __uint_as_float(h1 << 16);
    float r3 = v.w - __uint_as_float(h1 & 0xffff0000u);
    ((uint32_t*)hi)[2 * i + 0] = h0;
    ((uint32_t*)hi)[2 * i + 1] = h1;
    ((uint32_t*)lo)[2 * i + 0] = pack_bf16x2(r0, r1);
    ((uint32_t*)lo)[2 * i + 1] = pack_bf16x2(r2, r3);
}

__global__ __launch_bounds__(256) void convert_x(const float* __restrict__ src_in,
                                                 int n4, int from_gao)
{
    int i = blockIdx.x * blockDim.x + threadIdx.x;
    if (i >= n4) return;
    const float* src = from_gao ? g_ao : src_in;
    split_store(g_xhi, g_xlo, i, ((const float4*)src)[i]);
}

__global__ __launch_bounds__(256) void convert_w(const float* __restrict__ w0,
                                                 const float* __restrict__ w1,
                                                 const float* __restrict__ w2,
                                                 const float* __restrict__ w3,
                                                 int n4)
{
    int i = blockIdx.x * blockDim.x + threadIdx.x;
    if (i >= n4) return;
    int wi = blockIdx.y;
    const float* src = (wi == 0) ? w0 : (wi == 1) ? w1 : (wi == 2) ? w2 : w3;
    split_store(g_whi + (size_t)wi * EMB * EMB,
                g_wlo + (size_t)wi * EMB * EMB, i, ((const float4*)src)[i]);
}

// ---------------------------------------------------------------------------
// mma.sync bf16-split GEMM: C = A(4096x768) @ W^T + bias.
// mode = base_mode + blockIdx.z. mode 0/1/2 -> q/k/v bf16 hi/lo [h][tok][64];
// mode 3 -> fp32 outp [N][768]. Weight widx = mode.
// Block 64(M) x 64(N), 4 warps. ldmatrix fragments, cp.async loads.
// ---------------------------------------------------------------------------
__global__ __launch_bounds__(128) void gemm_tc(const float* __restrict__ b0,
                                               const float* __restrict__ b1,
                                               const float* __restrict__ b2,
                                               float* __restrict__ outp,
                                               int base_mode)
{
    __shared__ __nv_bfloat16 Ah[64][PADB], Al[64][PADB];
    __shared__ __nv_bfloat16 Bh[64][PADB], Bl[64][PADB];

    int mode = base_mode + blockIdx.z;
    const float* bias = (blockIdx.z == 0) ? b0 : (blockIdx.z == 1) ? b1 : b2;
    const __nv_bfloat16* wh = g_whi + (size_t)mode * EMB * EMB;
    const __nv_bfloat16* wl = g_wlo + (size_t)mode * EMB * EMB;

    int nb = blockIdx.x * 64, mb = blockIdx.y * 64;
    int tid = threadIdx.x, w = tid >> 5, lane = tid & 31;
    int qr = lane >> 2, qc = (lane & 3) * 2;

    uint32_t sAh = sptr(&Ah[0][0]), sAl = sptr(&Al[0][0]);
    uint32_t sBh = sptr(&Bh[0][0]), sBl = sptr(&Bl[0][0]);

    // ldmatrix lane addressing
    int a_r = w * 16 + (lane & 7) + ((lane >> 3) & 1) * 8;
    int a_cb = ((lane >> 4) & 1) * 16;                   // byte offset of k-half
    int b_rl = (lane & 7) + ((lane >> 4) & 1) * 8;       // row within 16-n block
    int b_cb = ((lane >> 3) & 1) * 16;

    float acc[8][4];
    #pragma unroll
    for (int n = 0; n < 8; n++)
        #pragma unroll
        for (int j = 0; j < 4; j++) acc[n][j] = 0.f;

    for (int kc = 0; kc < EMB / 64; kc++) {
        __syncthreads();
        #pragma unroll
        for (int i = 0; i < 4; i++) {
            int idx = tid + i * 128;
            int r = idx >> 3, cb = (idx & 7) * 16;
            const char* ga = (const char*)(g_xhi + (size_t)(mb + r) * EMB + kc * 64) + cb;
            const char* gal = (const char*)(g_xlo + (size_t)(mb + r) * EMB + kc * 64) + cb;
            const char* gb = (const char*)(wh + (size_t)(nb + r) * EMB + kc * 64) + cb;
            const char* gbl = (const char*)(wl + (size_t)(nb + r) * EMB + kc * 64) + cb;
            uint32_t so = (uint32_t)(r * (PADB * 2) + cb);
            CP16(sAh + so, ga);
            CP16(sAl + so, gal);
            CP16(sBh + so, gb);
            CP16(sBl + so, gbl);
        }
        CP_COMMIT();
        CP_WAIT0();
        __syncthreads();

        #pragma unroll
        for (int t = 0; t < 4; t++) {
            uint32_t ah[4], al[4];
            uint32_t aoff = (uint32_t)(a_r * (PADB * 2) + t * 32 + a_cb);
            LDM_X4(ah, sAh + aoff);
            LDM_X4(al, sAl + aoff);
            #pragma unroll
            for (int nbk = 0; nbk < 4; nbk++) {
                uint32_t kh[4], kl[4];
                uint32_t boff = (uint32_t)((nbk * 16 + b_rl) * (PADB * 2) + t * 32 + b_cb);
                LDM_X4(kh, sBh + boff);
                LDM_X4(kl, sBl + boff);
                MMA_BF16(acc[2 * nbk], ah, kh[0], kh[1]);
                MMA_BF16(acc[2 * nbk], ah, kl[0], kl[1]);
                MMA_BF16(acc[2 * nbk], al, kh[0], kh[1]);
                MMA_BF16(acc[2 * nbk + 1], ah, kh[2], kh[3]);
                MMA_BF16(acc[2 * nbk + 1], ah, kl[2], kl[3]);
                MMA_BF16(acc[2 * nbk + 1], al, kh[2], kh[3]);
            }
        }
    }

    int r0 = mb + w * 16 + qr;
    if (mode == 3) {
        #pragma unroll
        for (int n = 0; n < 8; n++) {
            int col = nb + n * 8 + qc;
            float2 v0 = {acc[n][0] + bias[col], acc[n][1] + bias[col + 1]};
            float2 v1 = {acc[n][2] + bias[col], acc[n][3] + bias[col + 1]};
            *(float2*)(outp + (size_t)r0 * EMB + col) = v0;
            *(float2*)(outp + (size_t)(r0 + 8) * EMB + col) = v1;
        }
    } else {
        __nv_bfloat16* dh = (mode == 0) ? g_qhi : (mode == 1) ? g_khi : g_vhi;
        __nv_bfloat16* dl = (mode == 0) ? g_qlo : (mode == 1) ? g_klo : g_vlo;
        int hh = blockIdx.x;
        #pragma unroll
        for (int n = 0; n < 8; n++) {
            int d = n * 8 + qc;
            float bb0 = bias[nb + d], bb1 = bias[nb + d + 1];
            #pragma unroll
            for (int half = 0; half < 2; half++) {
                float v0 = acc[n][half * 2 + 0] + bb0;
                float v1 = acc[n][half * 2 + 1] + bb1;
                uint32_t ph = pack_bf16x2(v0, v1);
                float e0 = v0 - __uint_as_float(ph << 16);
                float e1 = v1 - __uint_as_float(ph & 0xffff0000u);
                size_t off = ((size_t)hh * NTOK + r0 + half * 8) * HD + d;
                *(uint32_t*)(dh + off) = ph;
                *(uint32_t*)(dl + off) = pack_bf16x2(e0, e1);
            }
        }
    }
}

// ---------------------------------------------------------------------------
// V transpose: g_v{hi,lo} [h][tok][64] -> g_vt{hi,lo} [h][64][tok]
// ---------------------------------------------------------------------------
__global__ __launch_bounds__(256) void transpose_v()
{
    __shared__ __nv_bfloat16 th[64][PADB], tl[64][PADB];
    int h = blockIdx.y, j0 = blockIdx.x * 64, tid = threadIdx.x;

    for (int idx = tid; idx < 512; idx += 256) {
        int r = idx >> 3, c = idx & 7;
        const char* sh = (const char*)(g_vhi + ((size_t)h * NTOK + j0 + r) * HD) + c * 16;
        const char* sl = (const char*)(g_vlo + ((size_t)h * NTOK + j0 + r) * HD) + c * 16;
        *(uint4*)((char*)&th[r][0] + c * 16) = *(const uint4*)sh;
        *(uint4*)((char*)&tl[r][0] + c * 16) = *(const uint4*)sl;
    }
    __syncthreads();

    for (int odx = tid; odx < 2048; odx += 256) {
        int d = odx >> 5, tk = (odx & 31) * 2;
        uint32_t ph = ((uint32_t)__bfloat16_as_ushort(th[tk][d])) |
                      ((uint32_t)__bfloat16_as_ushort(th[tk + 1][d]) << 16);
        uint32_t pl = ((uint32_t)__bfloat16_as_ushort(tl[tk][d])) |
                      ((uint32_t)__bfloat16_as_ushort(tl[tk + 1][d]) << 16);
        size_t off = ((size_t)h * HD + d) * NTOK + j0 + tk;
        *(uint32_t*)(g_vthi + off) = ph;
        *(uint32_t*)(g_vtlo + off) = pl;
    }
}

// ---------------------------------------------------------------------------
// Tensor-core flash attention. Block = 64 queries x 1 head, 4 warps.
// ldmatrix B-fragments, cp.async tile loads, poly-exp2 softmax,
// sparse bias via per-tile u8 count scatter.
// ---------------------------------------------------------------------------
__global__ __launch_bounds__(128) void attn_tc(const int* __restrict__ sim)
{
    __shared__ __nv_bfloat16 Kh[64][PADB], Kl[64][PADB];
    __shared__ __nv_bfloat16 Vh[64][PADB], Vl[64][PADB];   // [d][tok]
    __shared__ __align__(16) unsigned char bc[64][64];
    __shared__ int sims[640];

    int h = blockIdx.y, i0 = blockIdx.x * 64;
    int tid = threadIdx.x, w = tid >> 5, lane = tid & 31;
    int qr = lane >> 2, qc = (lane & 3) * 2;

    for (int t = tid; t < 640; t += 128) sims[t] = sim[(size_t)i0 * 10 + t];

    // Persistent Q fragments from global
    uint32_t qh[4][4], ql[4][4];
    {
        const __nv_bfloat16* qbh = g_qhi + ((size_t)h * NTOK + i0 + w * 16) * HD;
        const __nv_bfloat16* qbl = g_qlo + ((size_t)h * NTOK + i0 + w * 16) * HD;
        #pragma unroll
        for (int t = 0; t < 4; t++)
            #pragma unroll
            for (int j = 0; j < 4; j++) {
                int r = qr + (j & 1) * 8;
                int c = t * 16 + qc + (j >> 1) * 8;
                qh[t][j] = *(const uint32_t*)(qbh + (size_t)r * HD + c);
                ql[t][j] = *(const uint32_t*)(qbl + (size_t)r * HD + c);
            }
    }

    const __nv_bfloat16* kbh = g_khi + (size_t)h * NTOK * HD;
    const __nv_bfloat16* kbl = g_klo + (size_t)h * NTOK * HD;
    const __nv_bfloat16* vbh = g_vthi + (size_t)h * HD * NTOK;
    const __nv_bfloat16* vbl = g_vtlo + (size_t)h * HD * NTOK;

    uint32_t sKh = sptr(&Kh[0][0]), sKl = sptr(&Kl[0][0]);
    uint32_t sVh = sptr(&Vh[0][0]), sVl = sptr(&Vl[0][0]);

    int b_rl = (lane & 7) + ((lane >> 4) & 1) * 8;
    int b_cb = ((lane >> 3) & 1) * 16;

    float o[8][4];
    #pragma unroll
    for (int n = 0; n < 8; n++)
        #pragma unroll
        for (int j = 0; j < 4; j++) o[n][j] = 0.f;
    float m0 = -1e30f, m1 = -1e30f, l0 = 0.f, l1 = 0.f;
    int br0 = w * 16 + qr, br1 = br0 + 8;

    for (int kt = 0; kt < NTOK / 64; kt++) {
        int j0 = kt * 64;
        __syncthreads();
        #pragma unroll
        for (int i = 0; i < 4; i++) {
            int idx = tid + i * 128;
            int r = idx >> 3, cb = (idx & 7) * 16;
            uint32_t so = (uint32_t)(r * (PADB * 2) + cb);
            CP16(sKh + so, (const char*)(kbh + (size_t)(j0 + r) * HD) + cb);
            CP16(sKl + so, (const char*)(kbl + (size_t)(j0 + r) * HD) + cb);
            CP16(sVh + so, (const char*)(vbh + (size_t)r * NTOK + j0) + cb);
            CP16(sVl + so, (const char*)(vbl + (size_t)r * NTOK + j0) + cb);
        }
        CP_COMMIT();
        for (int idx = tid; idx < 256; idx += 128)
            *(uint4*)(&bc[0][0] + idx * 16) = make_uint4(0u, 0u, 0u, 0u);
        CP_WAIT0();
        __syncthreads();
        if (tid < 64) {
            #pragma unroll
            for (int s5 = 0; s5 < 10; s5++) {
                int rel = sims[tid * 10 + s5] - j0;
                if ((unsigned)rel < 64u) bc[tid][rel]++;
            }
        }
        __syncthreads();

        // ---- S = Q K^T (3-pass bf16 split) ----
        float s[8][4];
        #pragma unroll
        for (int n = 0; n < 8; n++)
            #pragma unroll
            for (int j = 0; j < 4; j++) s[n][j] = 0.f;
        #pragma unroll
        for (int t = 0; t < 4; t++) {
            #pragma unroll
            for (int nbk = 0; nbk < 4; nbk++) {
                uint32_t kh[4], kl[4];
                uint32_t boff = (uint32_t)((nbk * 16 + b_rl) * (PADB * 2) + t * 32 + b_cb);
                LDM_X4(kh, sKh + boff);
                LDM_X4(kl, sKl + boff);
                MMA_BF16(s[2 * nbk], qh[t], kh[0], kh[1]);
                MMA_BF16(s[2 * nbk], qh[t], kl[0], kl[1]);
                MMA_BF16(s[2 * nbk], ql[t], kh[0], kh[1]);
                MMA_BF16(s[2 * nbk + 1], qh[t], kh[2], kh[3]);
                MMA_BF16(s[2 * nbk + 1], qh[t], kl[2], kl[3]);
                MMA_BF16(s[2 * nbk + 1], ql[t], kh[2], kh[3]);
            }
        }

        // ---- scale + bias + online softmax ----
        float mx0 = -1e30f, mx1 = -1e30f;
        #pragma unroll
        for (int n = 0; n < 8; n++) {
            int c0i = n * 8 + qc;
            s[n][0] = fmaf(s[n][0], 0.125f, (float)bc[br0][c0i]);
            s[n][1] = fmaf(s[n][1], 0.125f, (float)bc[br0][c0i + 1]);
            s[n][2] = fmaf(s[n][2], 0.125f, (float)bc[br1][c0i]);
            s[n][3] = fmaf(s[n][3], 0.125f, (float)bc[br1][c0i + 1]);
            mx0 = fmaxf(mx0, fmaxf(s[n][0], s[n][1]));
            mx1 = fmaxf(mx1, fmaxf(s[n][2], s[n][3]));
        }
        #pragma unroll
        for (int off = 1; off <= 2; off <<= 1) {
            mx0 = fmaxf(mx0, __shfl_xor_sync(0xffffffffu, mx0, off));
            mx1 = fmaxf(mx1, __shfl_xor_sync(0xffffffffu, mx1, off));
        }
        float mn0 = fmaxf(m0, mx0), mn1 = fmaxf(m1, mx1);
        float a0 = exp2p((m0 - mn0) * L2E), a1 = exp2p((m1 - mn1) * L2E);

        float rs0 = 0.f, rs1 = 0.f;
        uint32_t pa[4][4], pl[4][4];
        #pragma unroll
        for (int n = 0; n < 8; n++) {
            float p0 = exp2p((s[n][0] - mn0) * L2E);
            float p1 = exp2p((s[n][1] - mn0) * L2E);
            float p2 = exp2p((s[n][2] - mn1) * L2E);
            float p3 = exp2p((s[n][3] - mn1) * L2E);
            rs0 += p0 + p1;
            rs1 += p2 + p3;
            uint32_t hp01 = pack_bf16x2(p0, p1);
            uint32_t hp23 = pack_bf16x2(p2, p3);
            float e0 = p0 - __uint_as_float(hp01 << 16);
            float e1 = p1 - __uint_as_float(hp01 & 0xffff0000u);
            float e2 = p2 - __uint_as_float(hp23 << 16);
            float e3 = p3 - __uint_as_float(hp23 & 0xffff0000u);
            int t = n >> 1, half = (n & 1) * 2;
            pa[t][half + 0] = hp01;
            pa[t][half + 1] = hp23;
            pl[t][half + 0] = pack_bf16x2(e0, e1);
            pl[t][half + 1] = pack_bf16x2(e2, e3);
        }
        #pragma unroll
        for (int off = 1; off <= 2; off <<= 1) {
            rs0 += __shfl_xor_sync(0xffffffffu, rs0, off);
            rs1 += __shfl_xor_sync(0xffffffffu, rs1, off);
        }
        l0 = l0 * a0 + rs0;
        l1 = l1 * a1 + rs1;
        m0 = mn0;
        m1 = mn1;
        #pragma unroll
        for (int n = 0; n < 8; n++) {
            o[n][0] *= a0; o[n][1] *= a0;
            o[n][2] *= a1; o[n][3] *= a1;
        }

        // ---- O += P V (3-pass bf16 split) ----
        #pragma unroll
        for (int t = 0; t < 4; t++) {
            #pragma unroll
            for (int nbk = 0; nbk < 4; nbk++) {
                uint32_t vh[4], vl[4];
                uint32_t boff = (uint32_t)((nbk * 16 + b_rl) * (PADB * 2) + t * 32 + b_cb);
                LDM_X4(vh, sVh + boff);
                LDM_X4(vl, sVl + boff);
                MMA_BF16(o[2 * nbk], pa[t], vh[0], vh[1]);
                MMA_BF16(o[2 * nbk], pa[t], vl[0], vl[1]);
                MMA_BF16(o[2 * nbk], pl[t], vh[0], vh[1]);
                MMA_BF16(o[2 * nbk + 1], pa[t], vh[2], vh[3]);
                MMA_BF16(o[2 * nbk + 1], pa[t], vl[2], vl[3]);
                MMA_BF16(o[2 * nbk + 1], pl[t], vh[2], vh[3]);
            }
        }
    }

    float il0 = 1.f / l0, il1 = 1.f / l1;
    #pragma unroll
    for (int n = 0; n < 8; n++) {
        int col = h * HD + n * 8 + qc;
        float2 v0 = {o[n][0] * il0, o[n][1] * il0};
        float2 v1 = {o[n][2] * il1, o[n][3] * il1};
        *(float2*)(g_ao + (size_t)(i0 + br0) * EMB + col) = v0;
        *(float2*)(g_ao + (size_t)(i0 + br1) * EMB + col) = v1;
    }
}

// ---------------------------------------------------------------------------
extern "C" void kernel_launch(void* const* d_in, const int* in_sizes, int n_in,
                              void* d_out, int out_size)
{
    const float* x   = (const float*)d_in[0];
    const int*   sim = (const int*)d_in[1];
    const float* Wq  = (const float*)d_in[2];
    const float* bq  = (const float*)d_in[3];
    const float* Wk  = (const float*)d_in[4];
    const float* bk  = (const float*)d_in[5];
    const float* Wv  = (const float*)d_in[6];
    const float* bv  = (const float*)d_in[7];
    const float* Wo  = (const float*)d_in[8];
    const float* bo  = (const float*)d_in[9];
    float* out = (float*)d_out;

    const int n4x = NTOK * EMB / 4;
    const int n4w = EMB * EMB / 4;

    convert_x<<<n4x / 256, 256>>>(x, n4x, 0);
    convert_w<<<dim3(n4w / 256, 4), 256>>>(Wq, Wk, Wv, Wo, n4w);

    gemm_tc<<<dim3(EMB / 64, NTOK / 64, 3), 128>>>(bq, bk, bv, nullptr, 0);

    transpose_v<<<dim3(NTOK / 64, NH), 256>>>();
    attn_tc<<<dim3(NTOK / 64, NH), 128>>>(sim);

    convert_x<<<n4x / 256, 256>>>(nullptr, n4x, 1);
    gemm_tc<<<dim3(EMB / 64, NTOK / 64, 1), 128>>>(bo, nullptr, nullptr, out, 3);
}